// round 5
// baseline (speedup 1.0000x reference)
#include <cuda_runtime.h>
#include <cuda_bf16.h>
#include <stdint.h>

#define N_NODES_C  100000
#define N_GRAPHS_C 128
#define D_NODE 96
#define D_EDGE 32
#define HID 16
#define BN_EPS 1e-5f

#define NT 256
#define EDGE_THREADS 256
#define TILE_B 1024        // edges per block (8 warps * 32 * 4 passes)
#define PASSES 4

// ---- folded parameters ----
struct CP {
    float W[D_EDGE][HID];    // folded edge-part of W1, [j][k]
    float B[HID];            // folded bias
    float W2[HID];
    float b2;
    float pad[3];
    float Wx[HID][D_NODE];   // folded node-part of W1, [k][j]
};
__constant__ CP c_par;       // for node kernel (uniform access)
__device__   CP g_par;       // master copy, also read by edge kernel

__device__ float g_p[N_NODES_C * HID];   // per-node first-layer partials (6.4 MB)

// -------- fold BN into weights; zero output --------
__global__ void prep_kernel(const float* __restrict__ W1, const float* __restrict__ b1,
                            const float* __restrict__ gamma, const float* __restrict__ beta,
                            const float* __restrict__ rm, const float* __restrict__ rv,
                            const float* __restrict__ W2, const float* __restrict__ b2,
                            float* __restrict__ out, int out_n) {
    __shared__ float a[HID];
    int lt = threadIdx.x;
    int t  = blockIdx.x * blockDim.x + lt;
    int stride = gridDim.x * blockDim.x;
    if (lt < HID) a[lt] = gamma[lt] * rsqrtf(rv[lt] + BN_EPS);
    __syncthreads();
    for (int i = t; i < D_EDGE * HID; i += stride) {
        int j = i / HID, k = i % HID;
        g_par.W[j][k] = a[k] * W1[k * (D_NODE + D_EDGE) + D_NODE + j];
    }
    for (int i = t; i < HID * D_NODE; i += stride) {
        int k = i / D_NODE, j = i % D_NODE;
        g_par.Wx[k][j] = a[k] * W1[k * (D_NODE + D_EDGE) + j];
    }
    if (t < HID) {
        g_par.B[t]  = a[t] * (b1[t] - rm[t]) + beta[t];
        g_par.W2[t] = W2[t];
    }
    if (t == 0) g_par.b2 = b2[0];
    if (t < out_n) out[t] = 0.0f;
}

// -------- per-node: p[n][k] = Wx'[k] . x[n] --------
__global__ void __launch_bounds__(NT) node_kernel(const float* __restrict__ x, int n_nodes) {
    int n = blockIdx.x * blockDim.x + threadIdx.x;
    if (n >= n_nodes) return;
    float acc[HID];
#pragma unroll
    for (int k = 0; k < HID; k++) acc[k] = 0.0f;
    const float4* xr = (const float4*)(x + (size_t)n * D_NODE);
#pragma unroll
    for (int jj = 0; jj < D_NODE / 4; jj++) {
        float4 v = __ldg(xr + jj);
#pragma unroll
        for (int k = 0; k < HID; k++) {
            acc[k] += c_par.Wx[k][jj*4+0] * v.x + c_par.Wx[k][jj*4+1] * v.y
                    + c_par.Wx[k][jj*4+2] * v.z + c_par.Wx[k][jj*4+3] * v.w;
        }
    }
    float4* po = (float4*)(g_p + (size_t)n * HID);
    po[0] = make_float4(acc[0], acc[1], acc[2], acc[3]);
    po[1] = make_float4(acc[4], acc[5], acc[6], acc[7]);
    po[2] = make_float4(acc[8], acc[9], acc[10], acc[11]);
    po[3] = make_float4(acc[12], acc[13], acc[14], acc[15]);
}

// ---- helpers ----
__device__ __forceinline__ unsigned long long shflx64(unsigned long long v, int m) {
    unsigned lo = (unsigned)v, hi = (unsigned)(v >> 32);
    lo = __shfl_xor_sync(0xffffffffu, lo, m);
    hi = __shfl_xor_sync(0xffffffffu, hi, m);
    return ((unsigned long long)hi << 32) | lo;
}
__device__ __forceinline__ unsigned long long add2(unsigned long long x, unsigned long long y) {
    unsigned long long r;
    asm("add.rn.f32x2 %0,%1,%2;" : "=l"(r) : "l"(x), "l"(y));
    return r;
}

// -------- per-edge: octet-cooperative, no smem staging --------
__global__ void __launch_bounds__(EDGE_THREADS) edge_kernel(
    const float* __restrict__ edge_attr,
    const int* __restrict__ ei,             // [2][E] int32
    const int* __restrict__ batch,          // [N]    int32
    float* __restrict__ out,                // [G]
    int n_edges) {
    __shared__ float bins[N_GRAPHS_C];

    const int t    = threadIdx.x;
    const int warp = t >> 5;
    const int lane = t & 31;
    const int a    = lane >> 3;   // edge-sub within round
    const int c    = lane & 7;    // chunk / pair index

    if (t < N_GRAPHS_C) bins[t] = 0.0f;
    __syncthreads();

    // lane-constant folded weights: rows 4c..4c+3, as 8 packed pairs each
    unsigned long long Wr[4][8];
#pragma unroll
    for (int jj = 0; jj < 4; jj++)
#pragma unroll
        for (int p = 0; p < 8; p++)
            Wr[jj][p] = __ldg((const unsigned long long*)&g_par.W[4*c + jj][0] + p);
    const float blo  = __ldg(&g_par.B[2*c]);
    const float bhi  = __ldg(&g_par.B[2*c + 1]);
    const float w2lo = __ldg(&g_par.W2[2*c]);
    const float w2hi = __ldg(&g_par.W2[2*c + 1]);
    const float b2v  = __ldg(&g_par.b2);

    const float4* ga = (const float4*)edge_attr;
    const long long nf4 = (long long)n_edges * (D_EDGE / 4);

#pragma unroll 1
    for (int pass = 0; pass < PASSES; pass++) {
        const long long we0 = (long long)blockIdx.x * TILE_B + pass * 256 + warp * 32;
        if (we0 >= n_edges) break;

        // preload per-warp-tile edge metadata (lane i owns tile-edge i)
        const long long myE = we0 + lane;
        const bool mv = myE < n_edges;
        int s_pre = 0, g_pre = 0;
        if (mv) {
            s_pre = __ldg(ei + myE);
            int d  = __ldg(ei + n_edges + myE);
            g_pre  = __ldg(batch + d);
        }

#pragma unroll
        for (int r = 0; r < 8; r++) {
            const long long er = we0 + 4*r + a;       // edge this lane computes (chunk c)
            const long long fidx = we0 * 8 + 32*r + lane;
            float4 av = make_float4(0.f, 0.f, 0.f, 0.f);
            if (fidx < nf4) av = __ldg(ga + fidx);

            const int src = __shfl_sync(0xffffffffu, s_pre, 4*r + a);
            const int g   = __shfl_sync(0xffffffffu, g_pre, 4*r + a);

            float2 pp = make_float2(0.f, 0.f);
            if (er < n_edges) pp = __ldg((const float2*)g_p + (size_t)src * 8 + c);

            // partial pairs over this lane's 4 j's
            unsigned long long P[8];
#pragma unroll
            for (int p = 0; p < 8; p++) P[p] = 0ULL;
            float aj[4] = {av.x, av.y, av.z, av.w};
#pragma unroll
            for (int jj = 0; jj < 4; jj++) {
                unsigned long long adup;
                asm("mov.b64 %0,{%1,%1};" : "=l"(adup) : "f"(aj[jj]));
#pragma unroll
                for (int p = 0; p < 8; p++)
                    asm("fma.rn.f32x2 %0,%1,%2,%0;" : "+l"(P[p]) : "l"(Wr[jj][p]), "l"(adup));
            }

            // reduce-scatter over octet: lane c ends with pair index c
            const bool hi4 = (c & 4);
            unsigned long long k0 = hi4 ? P[4] : P[0], s0 = hi4 ? P[0] : P[4];
            unsigned long long k1 = hi4 ? P[5] : P[1], s1 = hi4 ? P[1] : P[5];
            unsigned long long k2 = hi4 ? P[6] : P[2], s2 = hi4 ? P[2] : P[6];
            unsigned long long k3 = hi4 ? P[7] : P[3], s3 = hi4 ? P[3] : P[7];
            k0 = add2(k0, shflx64(s0, 4));
            k1 = add2(k1, shflx64(s1, 4));
            k2 = add2(k2, shflx64(s2, 4));
            k3 = add2(k3, shflx64(s3, 4));
            const bool hi2 = (c & 2);
            unsigned long long m0 = hi2 ? k2 : k0, t0 = hi2 ? k0 : k2;
            unsigned long long m1 = hi2 ? k3 : k1, t1 = hi2 ? k1 : k3;
            m0 = add2(m0, shflx64(t0, 2));
            m1 = add2(m1, shflx64(t1, 2));
            const bool hi1 = (c & 1);
            unsigned long long keep = hi1 ? m1 : m0, u = hi1 ? m0 : m1;
            unsigned long long S = add2(keep, shflx64(u, 1));

            // tail: + p + bias, relu, W2 dot, octet sum
            float lo, hi;
            asm("mov.b64 {%0,%1},%2;" : "=f"(lo), "=f"(hi) : "l"(S));
            float h0 = fmaxf(lo + pp.x + blo, 0.0f);
            float h1 = fmaxf(hi + pp.y + bhi, 0.0f);
            float msg = fmaf(w2lo, h0, w2hi * h1);
            msg += __shfl_xor_sync(0xffffffffu, msg, 1);
            msg += __shfl_xor_sync(0xffffffffu, msg, 2);
            msg += __shfl_xor_sync(0xffffffffu, msg, 4);
            if (c == 0 && er < n_edges)
                atomicAdd(&bins[g], msg + b2v);
        }
    }

    __syncthreads();
    if (t < N_GRAPHS_C) atomicAdd(&out[t], bins[t]);
}

extern "C" void kernel_launch(void* const* d_in, const int* in_sizes, int n_in,
                              void* d_out, int out_size) {
    const float* x         = (const float*)d_in[0];
    const float* edge_attr = (const float*)d_in[1];
    const int*   ei        = (const int*)d_in[2];
    const int*   batch     = (const int*)d_in[3];
    const float* W1        = (const float*)d_in[4];
    const float* b1        = (const float*)d_in[5];
    const float* gamma     = (const float*)d_in[6];
    const float* beta      = (const float*)d_in[7];
    const float* rm        = (const float*)d_in[8];
    const float* rv        = (const float*)d_in[9];
    const float* W2        = (const float*)d_in[10];
    const float* b2        = (const float*)d_in[11];
    float* out = (float*)d_out;

    const int n_nodes = in_sizes[0] / D_NODE;
    const int n_edges = in_sizes[1] / D_EDGE;

    void *c_addr = nullptr, *g_addr = nullptr;
    cudaGetSymbolAddress(&c_addr, c_par);
    cudaGetSymbolAddress(&g_addr, g_par);

    prep_kernel<<<8, 256>>>(W1, b1, gamma, beta, rm, rv, W2, b2, out, out_size);
    cudaMemcpyAsync(c_addr, g_addr, sizeof(CP), cudaMemcpyDeviceToDevice, 0);
    node_kernel<<<(n_nodes + NT - 1) / NT, NT>>>(x, n_nodes);
    edge_kernel<<<(n_edges + TILE_B - 1) / TILE_B, EDGE_THREADS>>>(edge_attr, ei, batch, out, n_edges);
}

// round 6
// speedup vs baseline: 1.8484x; 1.8484x over previous
#include <cuda_runtime.h>
#include <cuda_bf16.h>
#include <stdint.h>

#define N_NODES_C  100000
#define N_GRAPHS_C 128
#define D_NODE 96
#define D_EDGE 32
#define HID 16
#define BN_EPS 1e-5f

#define TILE 256
#define THREADS 256
#define RSTRIDE 52        // floats per edge row: 32 attr + 16 p + 4 pad (conflict-free octet reads)
#define NT 256
#define NSLOT 32          // bin slots per graph (128B stride)

// ---- folded parameters ----
struct CP {
    float W[D_EDGE][HID];    // folded edge-part of W1, [j][k] (k-pairs contiguous)
    float B[HID];            // folded bias
    float W2[HID];
    float b2;
    float pad[3];
    float Wx[HID][D_NODE];   // folded node-part of W1, [k][j]
};
__constant__ CP c_par;
__device__   CP g_par;

__device__ float g_p[N_NODES_C * HID];            // per-node first-layer partials (6.4 MB)
__device__ float g_bins[N_GRAPHS_C * NSLOT];      // zero-init; finish kernel re-zeroes each launch

typedef unsigned long long u64;

__device__ __forceinline__ u64 add2(u64 x, u64 y) {
    u64 r; asm("add.rn.f32x2 %0,%1,%2;" : "=l"(r) : "l"(x), "l"(y)); return r;
}

// -------- fold BN into weights --------
__global__ void prep_kernel(const float* __restrict__ W1, const float* __restrict__ b1,
                            const float* __restrict__ gamma, const float* __restrict__ beta,
                            const float* __restrict__ rm, const float* __restrict__ rv,
                            const float* __restrict__ W2, const float* __restrict__ b2) {
    __shared__ float a[HID];
    int lt = threadIdx.x;
    int t  = blockIdx.x * blockDim.x + lt;
    int stride = gridDim.x * blockDim.x;
    if (lt < HID) a[lt] = gamma[lt] * rsqrtf(rv[lt] + BN_EPS);
    __syncthreads();
    for (int i = t; i < D_EDGE * HID; i += stride) {
        int j = i / HID, k = i % HID;
        g_par.W[j][k] = a[k] * W1[k * (D_NODE + D_EDGE) + D_NODE + j];
    }
    for (int i = t; i < HID * D_NODE; i += stride) {
        int k = i / D_NODE, j = i % D_NODE;
        g_par.Wx[k][j] = a[k] * W1[k * (D_NODE + D_EDGE) + j];
    }
    if (t < HID) {
        g_par.B[t]  = a[t] * (b1[t] - rm[t]) + beta[t];
        g_par.W2[t] = W2[t];
    }
    if (t == 0) g_par.b2 = b2[0];
}

// -------- per-node: p[n][k] = Wx'[k] . x[n] --------
__global__ void __launch_bounds__(NT) node_kernel(const float* __restrict__ x, int n_nodes) {
    int n = blockIdx.x * blockDim.x + threadIdx.x;
    if (n >= n_nodes) return;
    float acc[HID];
#pragma unroll
    for (int k = 0; k < HID; k++) acc[k] = 0.0f;
    const float4* xr = (const float4*)(x + (size_t)n * D_NODE);
#pragma unroll
    for (int jj = 0; jj < D_NODE / 4; jj++) {
        float4 v = __ldg(xr + jj);
#pragma unroll
        for (int k = 0; k < HID; k++) {
            acc[k] += c_par.Wx[k][jj*4+0] * v.x + c_par.Wx[k][jj*4+1] * v.y
                    + c_par.Wx[k][jj*4+2] * v.z + c_par.Wx[k][jj*4+3] * v.w;
        }
    }
    float4* po = (float4*)(g_p + (size_t)n * HID);
    po[0] = make_float4(acc[0], acc[1], acc[2], acc[3]);
    po[1] = make_float4(acc[4], acc[5], acc[6], acc[7]);
    po[2] = make_float4(acc[8], acc[9], acc[10], acc[11]);
    po[3] = make_float4(acc[12], acc[13], acc[14], acc[15]);
}

// -------- per-edge: packed-pair MLP + RED to global bins --------
__global__ void __launch_bounds__(THREADS) edge_kernel(
    const float* __restrict__ edge_attr,
    const int* __restrict__ ei,             // [2][E] int32
    const int* __restrict__ batch,          // [N]    int32
    int n_edges) {
    extern __shared__ float sm[];
    float* sRow = sm;                                   // TILE * RSTRIDE floats
    int*   sSrc = (int*)(sm + TILE * RSTRIDE);          // TILE

    const int t    = threadIdx.x;
    const int lane = t & 31;
    const int e0   = blockIdx.x * TILE;
    const int e    = e0 + t;
    const bool v   = e < n_edges;

    int src = 0, g = 0;
    if (v) {
        src = __ldg(ei + e);
        g   = __ldg(batch + __ldg(ei + n_edges + e));
    }
    sSrc[t] = src;
    __syncthreads();

    // stage edge_attr rows (coalesced LDG.128 -> STS.128)
    {
        const float4* ga = (const float4*)edge_attr;
        const long long base  = (long long)e0 * (D_EDGE / 4);
        const long long total = (long long)n_edges * (D_EDGE / 4);
#pragma unroll
        for (int r = 0; r < (TILE * (D_EDGE / 4)) / THREADS; r++) {   // 8 rounds
            int idx = r * THREADS + t;
            float4 w = make_float4(0.f, 0.f, 0.f, 0.f);
            if (base + idx < total) w = __ldg(ga + base + idx);
            int el = idx >> 3;
            int c  = idx & 7;
            *(float4*)(sRow + el * RSTRIDE + c * 4) = w;
        }
        // cooperative p gather: 4 lanes per edge -> 1 line per edge
#pragma unroll
        for (int r = 0; r < (TILE * 4) / THREADS; r++) {              // 4 rounds
            int idx = r * THREADS + t;
            int el  = idx >> 2;
            int q   = idx & 3;
            int s   = sSrc[el];
            float4 pv = __ldg((const float4*)g_p + (size_t)s * 4 + q);
            *(float4*)(sRow + el * RSTRIDE + D_EDGE + q * 4) = pv;
        }
    }
    __syncthreads();

    const float* myRow = sRow + t * RSTRIDE;
    const u64* cw = (const u64*)&c_par.W[0][0];     // [j][pair] packed
    const u64* cb = (const u64*)&c_par.B[0];

    // acc pairs = p + bias
    u64 A[8];
#pragma unroll
    for (int q = 0; q < 2; q++) {
        ulonglong2 pv0 = *(const ulonglong2*)(myRow + D_EDGE + q * 8);
        ulonglong2 pv1 = *(const ulonglong2*)(myRow + D_EDGE + q * 8 + 4);
        A[q*4+0] = add2(pv0.x, cb[q*4+0]);
        A[q*4+1] = add2(pv0.y, cb[q*4+1]);
        A[q*4+2] = add2(pv1.x, cb[q*4+2]);
        A[q*4+3] = add2(pv1.y, cb[q*4+3]);
    }

    // j-loop: packed FFMA2, weights via constant (uniform path)
#pragma unroll
    for (int c = 0; c < 8; c++) {
        float4 a4 = *(const float4*)(myRow + c * 4);
        float av[4] = {a4.x, a4.y, a4.z, a4.w};
#pragma unroll
        for (int jj = 0; jj < 4; jj++) {
            u64 adup;
            asm("mov.b64 %0,{%1,%1};" : "=l"(adup) : "f"(av[jj]));
            const u64* wrow = cw + (c*4 + jj) * 8;
#pragma unroll
            for (int p = 0; p < 8; p++) {
                u64 w = wrow[p];
                asm("fma.rn.f32x2 %0,%1,%2,%0;" : "+l"(A[p]) : "l"(w), "l"(adup));
            }
        }
    }

    if (v) {
        float m = c_par.b2;
#pragma unroll
        for (int p = 0; p < 8; p++) {
            float lo, hi;
            asm("mov.b64 {%0,%1},%2;" : "=f"(lo), "=f"(hi) : "l"(A[p]));
            m = fmaf(c_par.W2[2*p],   fmaxf(lo, 0.0f), m);
            m = fmaf(c_par.W2[2*p+1], fmaxf(hi, 0.0f), m);
        }
        atomicAdd(&g_bins[g * NSLOT + lane], m);   // RED.ADD, L2-side, spread slots
    }
}

// -------- finish: reduce bins -> out, then re-zero bins for next replay --------
__global__ void finish_kernel(float* __restrict__ out) {
    int t = threadIdx.x;           // 0..127
    float s = 0.0f;
#pragma unroll
    for (int i = 0; i < NSLOT; i++) s += g_bins[t * NSLOT + i];
    out[t] = s;
#pragma unroll
    for (int i = 0; i < NSLOT; i++) g_bins[t * NSLOT + i] = 0.0f;
}

#define EDGE_SMEM (TILE * RSTRIDE * 4 + TILE * 4)

extern "C" void kernel_launch(void* const* d_in, const int* in_sizes, int n_in,
                              void* d_out, int out_size) {
    const float* x         = (const float*)d_in[0];
    const float* edge_attr = (const float*)d_in[1];
    const int*   ei        = (const int*)d_in[2];
    const int*   batch     = (const int*)d_in[3];
    const float* W1        = (const float*)d_in[4];
    const float* b1        = (const float*)d_in[5];
    const float* gamma     = (const float*)d_in[6];
    const float* beta      = (const float*)d_in[7];
    const float* rm        = (const float*)d_in[8];
    const float* rv        = (const float*)d_in[9];
    const float* W2        = (const float*)d_in[10];
    const float* b2        = (const float*)d_in[11];
    float* out = (float*)d_out;

    const int n_nodes = in_sizes[0] / D_NODE;
    const int n_edges = in_sizes[1] / D_EDGE;

    cudaFuncSetAttribute(edge_kernel, cudaFuncAttributeMaxDynamicSharedMemorySize, EDGE_SMEM);

    void *c_addr = nullptr, *g_addr = nullptr;
    cudaGetSymbolAddress(&c_addr, c_par);
    cudaGetSymbolAddress(&g_addr, g_par);

    prep_kernel<<<8, 256>>>(W1, b1, gamma, beta, rm, rv, W2, b2);
    cudaMemcpyAsync(c_addr, g_addr, sizeof(CP), cudaMemcpyDeviceToDevice, 0);
    node_kernel<<<(n_nodes + NT - 1) / NT, NT>>>(x, n_nodes);
    edge_kernel<<<(n_edges + TILE - 1) / TILE, THREADS, EDGE_SMEM>>>(edge_attr, ei, batch, n_edges);
    finish_kernel<<<1, N_GRAPHS_C>>>(out);
}